// round 1
// baseline (speedup 1.0000x reference)
#include <cuda_runtime.h>

// ---- problem constants ----
#define BB 64
#define NN 128
#define TT 16
#define NUM_CLS 600
#define MAX_H 15
#define MAX_O 15
#define NMAX 30
#define MM 450            // MAX_H * NMAX
#define HUMAN_IDX 49
#define SCORE_TH 0.2f
#define NMS_TH 0.5f
#define PEXP 2.8f

#define BM (BB * MM)      // 28800

// float offsets in the flattened output (tuple order, all cast to f32)
#define OFF_BH   0                      // boxes_h  [B,M,4]   115200
#define OFF_BO   115200                 // boxes_o  [B,M,4]   115200
#define OFF_CLS  230400                 // obj_cls  [B,M]      28800
#define OFF_LAB  259200                 // lab_gt   [B,M,600] 17280000
#define OFF_PRI  17539200               // prior    [B,2,M,600] 34560000
#define OFF_PV   52099200               // pv       [B,M]      28800
// total = 52128000

// scratch (device globals: no allocation allowed)
__device__ unsigned int g_match[BM];
__device__ float        g_sh[BM];
__device__ float        g_so[BM];
__device__ int          g_cls[BM];

__device__ __forceinline__ float iou_raw(float4 a, float4 b) {
    float area_a = (a.z - a.x) * (a.w - a.y);
    float area_b = (b.z - b.x) * (b.w - b.y);
    float lx = fmaxf(a.x, b.x), ly = fmaxf(a.y, b.y);
    float rx = fminf(a.z, b.z), ry = fminf(a.w, b.w);
    float w = fmaxf(rx - lx, 0.0f), h = fmaxf(ry - ly, 0.0f);
    float inter = w * h;
    return inter / (area_a + area_b - inter + 1e-7f);
}

// ============================================================
// Kernel A: per-image NMS + selection + pair grid + small outputs
// 1 block per image, 128 threads (== N)
// ============================================================
__global__ __launch_bounds__(NN, 1)
void pairgen_select_kernel(const float* __restrict__ boxes,
                           const float* __restrict__ scores,
                           const int*   __restrict__ labels,
                           const float* __restrict__ tbh,
                           const float* __restrict__ tbo,
                           float* __restrict__ out) {
    __shared__ float4 sb[NN];
    __shared__ float  ss[NN];
    __shared__ int    sl[NN];
    __shared__ unsigned int adj[NN][4];
    __shared__ int    order[NN];
    __shared__ unsigned int keptMask[4];
    __shared__ float  spk[NN];
    __shared__ float4 coords[NMAX];
    __shared__ int    labp[NMAX];
    __shared__ float  scp[NMAX];
    __shared__ int    s_nh, s_nt;
    __shared__ float4 stbh[TT], stbo[TT];

    const int b   = blockIdx.x;
    const int tid = threadIdx.x;

    // ---- load per-image data ----
    sb[tid] = ((const float4*)boxes)[b * NN + tid];
    ss[tid] = scores[b * NN + tid];
    sl[tid] = labels[b * NN + tid];
    if (tid < TT) {
        stbh[tid] = ((const float4*)tbh)[b * TT + tid];
        stbo[tid] = ((const float4*)tbo)[b * TT + tid];
    }
    __syncthreads();

    // ---- score order (desc, valid first, stable) + NMS adjacency ----
    {
        const int i = tid;
        const float si = ss[i];
        const float ki = (si >= SCORE_TH) ? si : -1.0f;
        int r = 0;
        const float4 bi = sb[i];
        const int li = sl[i];
        unsigned int m0 = 0, m1 = 0, m2 = 0, m3 = 0;
        #pragma unroll 4
        for (int j = 0; j < NN; j++) {
            const float sj = ss[j];
            const float kj = (sj >= SCORE_TH) ? sj : -1.0f;
            r += (kj > ki) || (kj == ki && j < i);
            // class-aware suppression: different class => IoU(offset boxes) == 0
            bool sup = (sl[j] == li) && (iou_raw(bi, sb[j]) > NMS_TH);
            unsigned int bit = sup ? 1u : 0u;
            if (j < 32)       m0 |= bit << j;
            else if (j < 64)  m1 |= bit << (j - 32);
            else if (j < 96)  m2 |= bit << (j - 64);
            else              m3 |= bit << (j - 96);
        }
        order[r] = i;
        adj[i][0] = m0; adj[i][1] = m1; adj[i][2] = m2; adj[i][3] = m3;
    }
    __syncthreads();

    // ---- serial greedy NMS scan (thread 0, bitmask ops) ----
    if (tid == 0) {
        unsigned int sup0 = 0, sup1 = 0, sup2 = 0, sup3 = 0;
        unsigned int k0 = 0, k1 = 0, k2 = 0, k3 = 0;
        for (int i = 0; i < NN; i++) {
            const int idx = order[i];
            if (ss[idx] < SCORE_TH) break;     // sorted: rest are invalid
            const int w = idx >> 5, p = idx & 31;
            unsigned int sw = (w == 0) ? sup0 : (w == 1) ? sup1 : (w == 2) ? sup2 : sup3;
            if ((sw >> p) & 1u) continue;
            if (w == 0) k0 |= 1u << p; else if (w == 1) k1 |= 1u << p;
            else if (w == 2) k2 |= 1u << p; else k3 |= 1u << p;
            sup0 |= adj[idx][0]; sup1 |= adj[idx][1];
            sup2 |= adj[idx][2]; sup3 |= adj[idx][3];
        }
        keptMask[0] = k0; keptMask[1] = k1; keptMask[2] = k2; keptMask[3] = k3;
        s_nh = 0; s_nt = 0;
    }
    __syncthreads();

    // ---- top-k per group + perm key ----
    {
        const int i = tid;
        const bool kept = (keptMask[i >> 5] >> (i & 31)) & 1u;
        const bool ish  = (sl[i] == HUMAN_IDX);
        const float si  = ss[i];
        int rh = 0, ro = 0;
        #pragma unroll 4
        for (int j = 0; j < NN; j++) {
            const bool keptj = (keptMask[j >> 5] >> (j & 31)) & 1u;
            const bool ishj  = (sl[j] == HUMAN_IDX);
            const float sj   = ss[j];
            const bool better = (sj > si) || (sj == si && j < i);
            rh += (keptj &&  ishj && better);
            ro += (keptj && !ishj && better);
        }
        const bool selh = kept &&  ish && (rh < MAX_H);
        const bool selo = kept && !ish && (ro < MAX_O);
        spk[i] = selh ? -si : (selo ? (2.0f - si) : 1e9f);
        if (selh) atomicAdd(&s_nh, 1);
        if (selh || selo) atomicAdd(&s_nt, 1);
    }
    __syncthreads();

    // ---- permutation: rank by perm key (asc, stable), keep first 30 ----
    {
        const int i = tid;
        const float pki = spk[i];
        int pr = 0;
        #pragma unroll 4
        for (int j = 0; j < NN; j++) {
            const float pkj = spk[j];
            pr += (pkj < pki) || (pkj == pki && j < i);
        }
        if (pr < NMAX) {
            coords[pr] = sb[i];
            labp[pr]   = sl[i];
            scp[pr]    = ss[i];
        }
    }
    __syncthreads();

    const int nh = s_nh;
    const int nt = s_nt;

    // ---- pair grid: small outputs + scratch for expansion kernel ----
    float4* out_bh  = (float4*)(out + OFF_BH);
    float4* out_bo  = (float4*)(out + OFF_BO);
    float*  out_cls = out + OFF_CLS;
    float*  out_pv  = out + OFF_PV;

    for (int m = tid; m < MM; m += NN) {
        const int x = m / NMAX;
        const int y = m - x * NMAX;
        const bool pv = (x < nh) && (y < nt) && (x != y);
        float4 bh = make_float4(0.f, 0.f, 0.f, 0.f);
        float4 bo = bh;
        unsigned int mask = 0;
        float sh = 0.f, so = 0.f;
        int cls = 0;
        if (pv) {
            bh = coords[x];
            bo = coords[y];
            cls = labp[y];
            #pragma unroll
            for (int t = 0; t < TT; t++) {
                float ih = iou_raw(bh, stbh[t]);
                float io = iou_raw(bo, stbo[t]);
                if (fminf(ih, io) >= 0.5f) mask |= (1u << t);
            }
            sh = powf(scp[x], PEXP);
            so = powf(scp[y], PEXP);
        }
        const int row = b * MM + m;
        out_bh[row]  = bh;
        out_bo[row]  = bo;
        out_cls[row] = pv ? (float)cls : 0.0f;
        out_pv[row]  = pv ? 1.0f : 0.0f;
        g_match[row] = mask;
        g_sh[row] = sh;
        g_so[row] = so;
        g_cls[row] = cls;
    }
}

// ============================================================
// Kernel B: expand lab_gt [B,M,600] and prior [B,2,M,600]
// 1 warp per pair-row, 4 warps per block => 7200 blocks
// ============================================================
__global__ __launch_bounds__(128, 8)
void pairgen_expand_kernel(const int* __restrict__ gt_labels,
                           const float* __restrict__ mapping,
                           float* __restrict__ out) {
    const int wid  = threadIdx.x >> 5;
    const int lane = threadIdx.x & 31;
    const int row  = blockIdx.x * 4 + wid;      // < BM
    const int b    = row / MM;
    const int m    = row - b * MM;

    const unsigned int mask = g_match[row];
    const float sh = g_sh[row];
    const float so = g_so[row];
    const int cls  = g_cls[row];

    float4* lab = (float4*)(out + OFF_LAB) + (size_t)row * 150;
    float4* pr0 = (float4*)(out + OFF_PRI) + ((size_t)b * 2 * MM + m) * 150;
    float4* pr1 = pr0 + (size_t)MM * 150;

    if (sh == 0.0f) {   // invalid pair (pv false): all three rows are zero
        const float4 z = make_float4(0.f, 0.f, 0.f, 0.f);
        #pragma unroll
        for (int i = lane; i < 150; i += 32) {
            lab[i] = z; pr0[i] = z; pr1[i] = z;
        }
        return;
    }

    __shared__ unsigned int bmp[4][20];
    if (lane < 19) bmp[wid][lane] = 0;
    __syncwarp();
    if (lane < TT && ((mask >> lane) & 1u)) {
        int c = gt_labels[b * TT + lane];
        atomicOr(&bmp[wid][c >> 5], 1u << (c & 31));
    }
    __syncwarp();

    const float4* mr = (const float4*)(mapping + cls * NUM_CLS);
    #pragma unroll
    for (int i = lane; i < 150; i += 32) {
        const float4 mv = mr[i];
        pr0[i] = make_float4(mv.x * sh, mv.y * sh, mv.z * sh, mv.w * sh);
        pr1[i] = make_float4(mv.x * so, mv.y * so, mv.z * so, mv.w * so);
        const int c = i * 4;
        float4 lv;
        lv.x = ((bmp[wid][(c + 0) >> 5] >> ((c + 0) & 31)) & 1u) ? 1.0f : 0.0f;
        lv.y = ((bmp[wid][(c + 1) >> 5] >> ((c + 1) & 31)) & 1u) ? 1.0f : 0.0f;
        lv.z = ((bmp[wid][(c + 2) >> 5] >> ((c + 2) & 31)) & 1u) ? 1.0f : 0.0f;
        lv.w = ((bmp[wid][(c + 3) >> 5] >> ((c + 3) & 31)) & 1u) ? 1.0f : 0.0f;
        lab[i] = lv;
    }
}

extern "C" void kernel_launch(void* const* d_in, const int* in_sizes, int n_in,
                              void* d_out, int out_size) {
    const float* boxes     = (const float*)d_in[0];
    const float* scores    = (const float*)d_in[1];
    const int*   labels    = (const int*)  d_in[2];
    const float* t_boxes_h = (const float*)d_in[3];
    const float* t_boxes_o = (const float*)d_in[4];
    const int*   gt_labels = (const int*)  d_in[5];
    const float* mapping   = (const float*)d_in[6];
    float* out = (float*)d_out;

    pairgen_select_kernel<<<BB, NN>>>(boxes, scores, labels,
                                      t_boxes_h, t_boxes_o, out);
    pairgen_expand_kernel<<<BM / 4, 128>>>(gt_labels, mapping, out);
}

// round 2
// speedup vs baseline: 1.6674x; 1.6674x over previous
#include <cuda_runtime.h>

// ---- problem constants ----
#define BB 64
#define NN 128
#define TT 16
#define NUM_CLS 600
#define MAX_H 15
#define MAX_O 15
#define NMAX 30
#define MM 450            // MAX_H * NMAX
#define HUMAN_IDX 49
#define SCORE_TH 0.2f
#define NMS_TH 0.5f
#define PEXP 2.8f

#define BM (BB * MM)      // 28800

// float offsets in the flattened output (tuple order, all f32)
#define OFF_BH   0                      // boxes_h  [B,M,4]
#define OFF_BO   115200                 // boxes_o  [B,M,4]
#define OFF_CLS  230400                 // obj_cls  [B,M]
#define OFF_LAB  259200                 // lab_gt   [B,M,600]
#define OFF_PRI  17539200               // prior    [B,2,M,600]
#define OFF_PV   52099200               // pv       [B,M]
// zero-fill region: [OFF_LAB, OFF_PV) = 51,840,000 floats = 12,960,000 float4
#define ZERO_N4  12960000

// scratch (device globals: no allocation allowed)
__device__ unsigned int g_match[BM];
__device__ float        g_sh[BM];
__device__ float        g_so[BM];
__device__ int          g_cls[BM];

// IoU(a,b) > th  without division (denominator strictly positive)
__device__ __forceinline__ bool iou_gt(float4 a, float4 b, float th) {
    float area_a = (a.z - a.x) * (a.w - a.y);
    float area_b = (b.z - b.x) * (b.w - b.y);
    float w = fmaxf(fminf(a.z, b.z) - fmaxf(a.x, b.x), 0.0f);
    float h = fmaxf(fminf(a.w, b.w) - fmaxf(a.y, b.y), 0.0f);
    float inter = w * h;
    return inter > th * (area_a + area_b - inter + 1e-7f);
}
__device__ __forceinline__ bool iou_ge(float4 a, float4 b, float th) {
    float area_a = (a.z - a.x) * (a.w - a.y);
    float area_b = (b.z - b.x) * (b.w - b.y);
    float w = fmaxf(fminf(a.z, b.z) - fmaxf(a.x, b.x), 0.0f);
    float h = fmaxf(fminf(a.w, b.w) - fmaxf(a.y, b.y), 0.0f);
    float inter = w * h;
    return inter >= th * (area_a + area_b - inter + 1e-7f);
}

// ============================================================
// Kernel A: per-image NMS + selection + pair grid + small outputs
// 1 block per image, 128 threads (== N)
// ============================================================
__global__ __launch_bounds__(NN, 1)
void pairgen_select_kernel(const float* __restrict__ boxes,
                           const float* __restrict__ scores,
                           const int*   __restrict__ labels,
                           const float* __restrict__ tbh,
                           const float* __restrict__ tbo,
                           float* __restrict__ out) {
    __shared__ float4 sb[NN];
    __shared__ float  ss[NN];
    __shared__ int    sl[NN];
    __shared__ unsigned int adj[NN][4];
    __shared__ int    order[NN];
    __shared__ unsigned int keptMask[4];
    __shared__ float  spk[NN];
    __shared__ float4 coords[NMAX];
    __shared__ int    labp[NMAX];
    __shared__ float  scp[NMAX];
    __shared__ int    s_nh, s_nt;
    __shared__ float4 stbh[TT], stbo[TT];
    __shared__ unsigned int mbits_h[NMAX], mbits_o[NMAX];
    __shared__ float  pw[NMAX];

    const int b   = blockIdx.x;
    const int tid = threadIdx.x;

    // ---- load per-image data ----
    sb[tid] = ((const float4*)boxes)[b * NN + tid];
    ss[tid] = scores[b * NN + tid];
    sl[tid] = labels[b * NN + tid];
    if (tid < TT) {
        stbh[tid] = ((const float4*)tbh)[b * TT + tid];
        stbo[tid] = ((const float4*)tbo)[b * TT + tid];
    }
    __syncthreads();

    // ---- score order (desc, valid first, stable) + NMS adjacency ----
    {
        const int i = tid;
        const float si = ss[i];
        const float ki = (si >= SCORE_TH) ? si : -1.0f;
        int r = 0;
        const float4 bi = sb[i];
        const int li = sl[i];
        unsigned int m0 = 0, m1 = 0, m2 = 0, m3 = 0;
        #pragma unroll 8
        for (int j = 0; j < NN; j++) {
            const float sj = ss[j];
            const float kj = (sj >= SCORE_TH) ? sj : -1.0f;
            r += (kj > ki) || (kj == ki && j < i);
            // class-aware suppression: different class => IoU(offset boxes) == 0
            bool sup = (sl[j] == li) && iou_gt(bi, sb[j], NMS_TH);
            unsigned int bit = sup ? 1u : 0u;
            if (j < 32)       m0 |= bit << j;
            else if (j < 64)  m1 |= bit << (j - 32);
            else if (j < 96)  m2 |= bit << (j - 64);
            else              m3 |= bit << (j - 96);
        }
        order[r] = i;
        adj[i][0] = m0; adj[i][1] = m1; adj[i][2] = m2; adj[i][3] = m3;
    }
    __syncthreads();

    // ---- serial greedy NMS scan (thread 0, bitmask ops) ----
    if (tid == 0) {
        unsigned int sup0 = 0, sup1 = 0, sup2 = 0, sup3 = 0;
        unsigned int k0 = 0, k1 = 0, k2 = 0, k3 = 0;
        for (int i = 0; i < NN; i++) {
            const int idx = order[i];
            if (ss[idx] < SCORE_TH) break;     // sorted: rest are invalid
            const int w = idx >> 5, p = idx & 31;
            unsigned int sw = (w == 0) ? sup0 : (w == 1) ? sup1 : (w == 2) ? sup2 : sup3;
            if ((sw >> p) & 1u) continue;
            if (w == 0) k0 |= 1u << p; else if (w == 1) k1 |= 1u << p;
            else if (w == 2) k2 |= 1u << p; else k3 |= 1u << p;
            sup0 |= adj[idx][0]; sup1 |= adj[idx][1];
            sup2 |= adj[idx][2]; sup3 |= adj[idx][3];
        }
        keptMask[0] = k0; keptMask[1] = k1; keptMask[2] = k2; keptMask[3] = k3;
        s_nh = 0; s_nt = 0;
    }
    __syncthreads();

    // ---- top-k per group + perm key ----
    {
        const int i = tid;
        const bool kept = (keptMask[i >> 5] >> (i & 31)) & 1u;
        const bool ish  = (sl[i] == HUMAN_IDX);
        const float si  = ss[i];
        int rh = 0, ro = 0;
        #pragma unroll 8
        for (int j = 0; j < NN; j++) {
            const bool keptj = (keptMask[j >> 5] >> (j & 31)) & 1u;
            const bool ishj  = (sl[j] == HUMAN_IDX);
            const float sj   = ss[j];
            const bool better = (sj > si) || (sj == si && j < i);
            rh += (keptj &&  ishj && better);
            ro += (keptj && !ishj && better);
        }
        const bool selh = kept &&  ish && (rh < MAX_H);
        const bool selo = kept && !ish && (ro < MAX_O);
        spk[i] = selh ? -si : (selo ? (2.0f - si) : 1e9f);
        if (selh) atomicAdd(&s_nh, 1);
        if (selh || selo) atomicAdd(&s_nt, 1);
    }
    __syncthreads();

    // ---- permutation: rank by perm key (asc, stable), keep first 30 ----
    {
        const int i = tid;
        const float pki = spk[i];
        int pr = 0;
        #pragma unroll 8
        for (int j = 0; j < NN; j++) {
            const float pkj = spk[j];
            pr += (pkj < pki) || (pkj == pki && j < i);
        }
        if (pr < NMAX) {
            coords[pr] = sb[i];
            labp[pr]   = sl[i];
            scp[pr]    = ss[i];
        }
    }
    __syncthreads();

    // ---- precompute per-index GT-match bitmasks and s^p ----
    if (tid < NMAX) {
        const float4 c = coords[tid];
        unsigned int bh = 0, bo = 0;
        #pragma unroll
        for (int t = 0; t < TT; t++) {
            if (iou_ge(c, stbh[t], 0.5f)) bh |= (1u << t);
            if (iou_ge(c, stbo[t], 0.5f)) bo |= (1u << t);
        }
        mbits_h[tid] = bh;
        mbits_o[tid] = bo;
        pw[tid] = __powf(scp[tid], PEXP);
    }
    __syncthreads();

    const int nh = s_nh;
    const int nt = s_nt;

    // ---- pair grid: small outputs + scratch for expansion kernel ----
    float4* out_bh  = (float4*)(out + OFF_BH);
    float4* out_bo  = (float4*)(out + OFF_BO);
    float*  out_cls = out + OFF_CLS;
    float*  out_pv  = out + OFF_PV;

    for (int m = tid; m < MM; m += NN) {
        const int x = m / NMAX;
        const int y = m - x * NMAX;
        const bool pv = (x < nh) && (y < nt) && (x != y);
        float4 bh = make_float4(0.f, 0.f, 0.f, 0.f);
        float4 bo = bh;
        unsigned int mask = 0;
        float sh = 0.f, so = 0.f;
        int cls = 0;
        if (pv) {
            bh = coords[x];
            bo = coords[y];
            cls = labp[y];
            mask = mbits_h[x] & mbits_o[y];
            sh = pw[x];
            so = pw[y];
        }
        const int row = b * MM + m;
        out_bh[row]  = bh;
        out_bo[row]  = bo;
        out_cls[row] = pv ? (float)cls : 0.0f;
        out_pv[row]  = pv ? 1.0f : 0.0f;
        g_match[row] = mask;
        g_sh[row] = sh;
        g_so[row] = so;
        g_cls[row] = cls;
    }
}

// ============================================================
// Kernel Z: pure streaming zero-fill of lab_gt + prior (207 MB)
// ============================================================
__global__ __launch_bounds__(256)
void pairgen_zero_kernel(float4* __restrict__ p) {
    const int stride = gridDim.x * blockDim.x;
    const float4 z = make_float4(0.f, 0.f, 0.f, 0.f);
    for (int i = blockIdx.x * blockDim.x + threadIdx.x; i < ZERO_N4; i += stride)
        p[i] = z;
}

// ============================================================
// Kernel B: expand valid rows only (early-exit for invalid)
// 1 warp per pair-row, 4 warps per block => 7200 blocks
// ============================================================
__global__ __launch_bounds__(128, 8)
void pairgen_expand_kernel(const int* __restrict__ gt_labels,
                           const float* __restrict__ mapping,
                           float* __restrict__ out) {
    const int wid  = threadIdx.x >> 5;
    const int lane = threadIdx.x & 31;
    const int row  = blockIdx.x * 4 + wid;      // < BM
    const float sh = g_sh[row];
    if (sh == 0.0f) return;                     // invalid: already zero-filled

    const int b    = row / MM;
    const int m    = row - b * MM;
    const unsigned int mask = g_match[row];
    const float so = g_so[row];
    const int cls  = g_cls[row];

    float4* lab = (float4*)(out + OFF_LAB) + (size_t)row * 150;
    float4* pr0 = (float4*)(out + OFF_PRI) + ((size_t)b * 2 * MM + m) * 150;
    float4* pr1 = pr0 + (size_t)MM * 150;

    __shared__ unsigned int bmp[4][20];
    if (lane < 19) bmp[wid][lane] = 0;
    __syncwarp();
    if (lane < TT && ((mask >> lane) & 1u)) {
        int c = gt_labels[b * TT + lane];
        atomicOr(&bmp[wid][c >> 5], 1u << (c & 31));
    }
    __syncwarp();

    const float4* mr = (const float4*)(mapping + cls * NUM_CLS);
    #pragma unroll
    for (int i = lane; i < 150; i += 32) {
        const float4 mv = mr[i];
        pr0[i] = make_float4(mv.x * sh, mv.y * sh, mv.z * sh, mv.w * sh);
        pr1[i] = make_float4(mv.x * so, mv.y * so, mv.z * so, mv.w * so);
        const int c = i * 4;
        float4 lv;
        lv.x = ((bmp[wid][(c + 0) >> 5] >> ((c + 0) & 31)) & 1u) ? 1.0f : 0.0f;
        lv.y = ((bmp[wid][(c + 1) >> 5] >> ((c + 1) & 31)) & 1u) ? 1.0f : 0.0f;
        lv.z = ((bmp[wid][(c + 2) >> 5] >> ((c + 2) & 31)) & 1u) ? 1.0f : 0.0f;
        lv.w = ((bmp[wid][(c + 3) >> 5] >> ((c + 3) & 31)) & 1u) ? 1.0f : 0.0f;
        lab[i] = lv;
    }
}

extern "C" void kernel_launch(void* const* d_in, const int* in_sizes, int n_in,
                              void* d_out, int out_size) {
    const float* boxes     = (const float*)d_in[0];
    const float* scores    = (const float*)d_in[1];
    const int*   labels    = (const int*)  d_in[2];
    const float* t_boxes_h = (const float*)d_in[3];
    const float* t_boxes_o = (const float*)d_in[4];
    const int*   gt_labels = (const int*)  d_in[5];
    const float* mapping   = (const float*)d_in[6];
    float* out = (float*)d_out;

    pairgen_zero_kernel<<<4736, 256>>>((float4*)(out + OFF_LAB));
    pairgen_select_kernel<<<BB, NN>>>(boxes, scores, labels,
                                      t_boxes_h, t_boxes_o, out);
    pairgen_expand_kernel<<<BM / 4, 128>>>(gt_labels, mapping, out);
}

// round 3
// speedup vs baseline: 1.7431x; 1.0454x over previous
#include <cuda_runtime.h>

// ---- problem constants ----
#define BB 64
#define NN 128
#define TT 16
#define NUM_CLS 600
#define MAX_H 15
#define MAX_O 15
#define NMAX 30
#define MM 450            // MAX_H * NMAX
#define HUMAN_IDX 49
#define SCORE_TH 0.2f
#define NMS_TH 0.5f
#define PEXP 2.8f

#define BM (BB * MM)      // 28800

// float offsets in the flattened output (tuple order, all f32)
#define OFF_BH   0                      // boxes_h  [B,M,4]
#define OFF_BO   115200                 // boxes_o  [B,M,4]
#define OFF_CLS  230400                 // obj_cls  [B,M]
#define OFF_LAB  259200                 // lab_gt   [B,M,600]
#define OFF_PRI  17539200               // prior    [B,2,M,600]
#define OFF_PV   52099200               // pv       [B,M]
// zero-fill region: [OFF_LAB, OFF_PV) = 51,840,000 floats = 12,960,000 float4
#define ZERO_N4  12960000
#define ZERO_BLOCKS 4736

#define VALID_BIT 0x80000000u

// packed per-row scratch: {mask|valid, cls, sh_bits, so_bits}
__device__ uint4 g_meta[BM];

// IoU(a,b) > th  without division (denominator strictly positive)
__device__ __forceinline__ bool iou_gt(float4 a, float4 b, float th) {
    float area_a = (a.z - a.x) * (a.w - a.y);
    float area_b = (b.z - b.x) * (b.w - b.y);
    float w = fmaxf(fminf(a.z, b.z) - fmaxf(a.x, b.x), 0.0f);
    float h = fmaxf(fminf(a.w, b.w) - fmaxf(a.y, b.y), 0.0f);
    float inter = w * h;
    return inter > th * (area_a + area_b - inter + 1e-7f);
}
__device__ __forceinline__ bool iou_ge(float4 a, float4 b, float th) {
    float area_a = (a.z - a.x) * (a.w - a.y);
    float area_b = (b.z - b.x) * (b.w - b.y);
    float w = fmaxf(fminf(a.z, b.z) - fmaxf(a.x, b.x), 0.0f);
    float h = fmaxf(fminf(a.w, b.w) - fmaxf(a.y, b.y), 0.0f);
    float inter = w * h;
    return inter >= th * (area_a + area_b - inter + 1e-7f);
}

// ============================================================
// Kernel 1 (fused): blocks [0,64) do per-image selection;
// blocks [64, 64+4736) zero-fill lab_gt + prior.
// Select blocks are first in the grid -> scheduled in wave 1,
// so select runs concurrently under the zero-fill stream.
// ============================================================
__global__ __launch_bounds__(256, 6)
void pairgen_fused_kernel(const float* __restrict__ boxes,
                          const float* __restrict__ scores,
                          const int*   __restrict__ labels,
                          const float* __restrict__ tbh,
                          const float* __restrict__ tbo,
                          float* __restrict__ out) {
    // ---------------- zero-fill path ----------------
    if (blockIdx.x >= BB) {
        float4* p = (float4*)(out + OFF_LAB);
        const int stride = ZERO_BLOCKS * 256;
        const float4 z = make_float4(0.f, 0.f, 0.f, 0.f);
        for (int i = (blockIdx.x - BB) * 256 + threadIdx.x; i < ZERO_N4; i += stride)
            p[i] = z;
        return;
    }

    // ---------------- select path (one block per image) ----------------
    __shared__ float4 sb[NN];
    __shared__ float  ss[NN];
    __shared__ int    sl[NN];
    __shared__ unsigned int adj[NN][4];
    __shared__ int    order[NN];
    __shared__ unsigned int keptMask[4];
    __shared__ float  spk[NN];
    __shared__ float4 coords[NMAX];
    __shared__ int    labp[NMAX];
    __shared__ float  scp[NMAX];
    __shared__ int    s_nh, s_nt;
    __shared__ float4 stbh[TT], stbo[TT];
    __shared__ unsigned int mbits_h[NMAX], mbits_o[NMAX];
    __shared__ float  pw[NMAX];

    const int b   = blockIdx.x;
    const int tid = threadIdx.x;

    // ---- load per-image data ----
    if (tid < NN) {
        sb[tid] = ((const float4*)boxes)[b * NN + tid];
        ss[tid] = scores[b * NN + tid];
        sl[tid] = labels[b * NN + tid];
    }
    if (tid >= NN && tid < NN + TT) {
        stbh[tid - NN] = ((const float4*)tbh)[b * TT + (tid - NN)];
        stbo[tid - NN] = ((const float4*)tbo)[b * TT + (tid - NN)];
    }
    __syncthreads();

    // ---- score order (desc, valid first, stable) + NMS adjacency ----
    if (tid < NN) {
        const int i = tid;
        const float si = ss[i];
        const float ki = (si >= SCORE_TH) ? si : -1.0f;
        int r = 0;
        const float4 bi = sb[i];
        const int li = sl[i];
        unsigned int m0 = 0, m1 = 0, m2 = 0, m3 = 0;
        #pragma unroll 8
        for (int j = 0; j < NN; j++) {
            const float sj = ss[j];
            const float kj = (sj >= SCORE_TH) ? sj : -1.0f;
            r += (kj > ki) || (kj == ki && j < i);
            // class-aware suppression: different class => IoU(offset boxes) == 0
            bool sup = (sl[j] == li) && iou_gt(bi, sb[j], NMS_TH);
            unsigned int bit = sup ? 1u : 0u;
            if (j < 32)       m0 |= bit << j;
            else if (j < 64)  m1 |= bit << (j - 32);
            else if (j < 96)  m2 |= bit << (j - 64);
            else              m3 |= bit << (j - 96);
        }
        order[r] = i;
        adj[i][0] = m0; adj[i][1] = m1; adj[i][2] = m2; adj[i][3] = m3;
    }
    __syncthreads();

    // ---- serial greedy NMS scan (thread 0, bitmask ops) ----
    if (tid == 0) {
        unsigned int sup0 = 0, sup1 = 0, sup2 = 0, sup3 = 0;
        unsigned int k0 = 0, k1 = 0, k2 = 0, k3 = 0;
        for (int i = 0; i < NN; i++) {
            const int idx = order[i];
            if (ss[idx] < SCORE_TH) break;     // sorted: rest are invalid
            const int w = idx >> 5, p = idx & 31;
            unsigned int sw = (w == 0) ? sup0 : (w == 1) ? sup1 : (w == 2) ? sup2 : sup3;
            if ((sw >> p) & 1u) continue;
            if (w == 0) k0 |= 1u << p; else if (w == 1) k1 |= 1u << p;
            else if (w == 2) k2 |= 1u << p; else k3 |= 1u << p;
            sup0 |= adj[idx][0]; sup1 |= adj[idx][1];
            sup2 |= adj[idx][2]; sup3 |= adj[idx][3];
        }
        keptMask[0] = k0; keptMask[1] = k1; keptMask[2] = k2; keptMask[3] = k3;
        s_nh = 0; s_nt = 0;
    }
    __syncthreads();

    // ---- top-k per group + perm key ----
    if (tid < NN) {
        const int i = tid;
        const bool kept = (keptMask[i >> 5] >> (i & 31)) & 1u;
        const bool ish  = (sl[i] == HUMAN_IDX);
        const float si  = ss[i];
        int rh = 0, ro = 0;
        #pragma unroll 8
        for (int j = 0; j < NN; j++) {
            const bool keptj = (keptMask[j >> 5] >> (j & 31)) & 1u;
            const bool ishj  = (sl[j] == HUMAN_IDX);
            const float sj   = ss[j];
            const bool better = (sj > si) || (sj == si && j < i);
            rh += (keptj &&  ishj && better);
            ro += (keptj && !ishj && better);
        }
        const bool selh = kept &&  ish && (rh < MAX_H);
        const bool selo = kept && !ish && (ro < MAX_O);
        spk[i] = selh ? -si : (selo ? (2.0f - si) : 1e9f);
        if (selh) atomicAdd(&s_nh, 1);
        if (selh || selo) atomicAdd(&s_nt, 1);
    }
    __syncthreads();

    // ---- permutation: rank by perm key (asc, stable), keep first 30 ----
    if (tid < NN) {
        const int i = tid;
        const float pki = spk[i];
        int pr = 0;
        #pragma unroll 8
        for (int j = 0; j < NN; j++) {
            const float pkj = spk[j];
            pr += (pkj < pki) || (pkj == pki && j < i);
        }
        if (pr < NMAX) {
            coords[pr] = sb[i];
            labp[pr]   = sl[i];
            scp[pr]    = ss[i];
        }
    }
    __syncthreads();

    // ---- precompute per-index GT-match bitmasks and s^p ----
    if (tid < NMAX) {
        const float4 c = coords[tid];
        unsigned int bh = 0, bo = 0;
        #pragma unroll
        for (int t = 0; t < TT; t++) {
            if (iou_ge(c, stbh[t], 0.5f)) bh |= (1u << t);
            if (iou_ge(c, stbo[t], 0.5f)) bo |= (1u << t);
        }
        mbits_h[tid] = bh;
        mbits_o[tid] = bo;
        pw[tid] = __powf(scp[tid], PEXP);
    }
    __syncthreads();

    const int nh = s_nh;
    const int nt = s_nt;

    // ---- pair grid: small outputs + packed scratch (all 256 threads) ----
    float4* out_bh  = (float4*)(out + OFF_BH);
    float4* out_bo  = (float4*)(out + OFF_BO);
    float*  out_cls = out + OFF_CLS;
    float*  out_pv  = out + OFF_PV;

    for (int m = tid; m < MM; m += 256) {
        const int x = m / NMAX;
        const int y = m - x * NMAX;
        const bool pv = (x < nh) && (y < nt) && (x != y);
        float4 bh = make_float4(0.f, 0.f, 0.f, 0.f);
        float4 bo = bh;
        uint4 meta = make_uint4(0u, 0u, 0u, 0u);
        int cls = 0;
        if (pv) {
            bh = coords[x];
            bo = coords[y];
            cls = labp[y];
            meta.x = (mbits_h[x] & mbits_o[y]) | VALID_BIT;
            meta.y = (unsigned int)cls;
            meta.z = __float_as_uint(pw[x]);
            meta.w = __float_as_uint(pw[y]);
        }
        const int row = b * MM + m;
        out_bh[row]  = bh;
        out_bo[row]  = bo;
        out_cls[row] = pv ? (float)cls : 0.0f;
        out_pv[row]  = pv ? 1.0f : 0.0f;
        g_meta[row]  = meta;
    }
}

// ============================================================
// Kernel 2: expand valid rows only (single-load early-exit)
// 1 warp per pair-row, 4 warps per block => 7200 blocks
// ============================================================
__global__ __launch_bounds__(128, 16)
void pairgen_expand_kernel(const int* __restrict__ gt_labels,
                           const float* __restrict__ mapping,
                           float* __restrict__ out) {
    const int wid  = threadIdx.x >> 5;
    const int lane = threadIdx.x & 31;
    const int row  = blockIdx.x * 4 + wid;      // < BM
    const uint4 meta = g_meta[row];
    if (!(meta.x & VALID_BIT)) return;          // invalid: already zero-filled

    const int b    = row / MM;
    const int m    = row - b * MM;
    const unsigned int mask = meta.x;
    const int   cls = (int)meta.y;
    const float sh  = __uint_as_float(meta.z);
    const float so  = __uint_as_float(meta.w);

    float4* lab = (float4*)(out + OFF_LAB) + (size_t)row * 150;
    float4* pr0 = (float4*)(out + OFF_PRI) + ((size_t)b * 2 * MM + m) * 150;
    float4* pr1 = pr0 + (size_t)MM * 150;

    __shared__ unsigned int bmp[4][20];
    if (lane < 19) bmp[wid][lane] = 0;
    __syncwarp();
    if (lane < TT && ((mask >> lane) & 1u)) {
        int c = gt_labels[b * TT + lane];
        atomicOr(&bmp[wid][c >> 5], 1u << (c & 31));
    }
    __syncwarp();

    const float4* mr = (const float4*)(mapping + cls * NUM_CLS);
    #pragma unroll
    for (int i = lane; i < 150; i += 32) {
        const float4 mv = mr[i];
        pr0[i] = make_float4(mv.x * sh, mv.y * sh, mv.z * sh, mv.w * sh);
        pr1[i] = make_float4(mv.x * so, mv.y * so, mv.z * so, mv.w * so);
        const int c = i * 4;
        float4 lv;
        lv.x = ((bmp[wid][(c + 0) >> 5] >> ((c + 0) & 31)) & 1u) ? 1.0f : 0.0f;
        lv.y = ((bmp[wid][(c + 1) >> 5] >> ((c + 1) & 31)) & 1u) ? 1.0f : 0.0f;
        lv.z = ((bmp[wid][(c + 2) >> 5] >> ((c + 2) & 31)) & 1u) ? 1.0f : 0.0f;
        lv.w = ((bmp[wid][(c + 3) >> 5] >> ((c + 3) & 31)) & 1u) ? 1.0f : 0.0f;
        lab[i] = lv;
    }
}

extern "C" void kernel_launch(void* const* d_in, const int* in_sizes, int n_in,
                              void* d_out, int out_size) {
    const float* boxes     = (const float*)d_in[0];
    const float* scores    = (const float*)d_in[1];
    const int*   labels    = (const int*)  d_in[2];
    const float* t_boxes_h = (const float*)d_in[3];
    const float* t_boxes_o = (const float*)d_in[4];
    const int*   gt_labels = (const int*)  d_in[5];
    const float* mapping   = (const float*)d_in[6];
    float* out = (float*)d_out;

    pairgen_fused_kernel<<<BB + ZERO_BLOCKS, 256>>>(boxes, scores, labels,
                                                    t_boxes_h, t_boxes_o, out);
    pairgen_expand_kernel<<<BM / 4, 128>>>(gt_labels, mapping, out);
}

// round 4
// speedup vs baseline: 1.9801x; 1.1359x over previous
#include <cuda_runtime.h>

// ---- problem constants ----
#define BB 64
#define NN 128
#define TT 16
#define NUM_CLS 600
#define MAX_H 15
#define MAX_O 15
#define NMAX 30
#define MM 450            // MAX_H * NMAX
#define HUMAN_IDX 49
#define SCORE_TH 0.2f
#define NMS_TH 0.5f
#define PEXP 2.8f

#define BM (BB * MM)      // 28800

// float offsets in the flattened output (tuple order, all f32)
#define OFF_BH   0                      // boxes_h  [B,M,4]
#define OFF_BO   115200                 // boxes_o  [B,M,4]
#define OFF_CLS  230400                 // obj_cls  [B,M]
#define OFF_LAB  259200                 // lab_gt   [B,M,600]
#define OFF_PRI  17539200               // prior    [B,2,M,600]
#define OFF_PV   52099200               // pv       [B,M]
// zero-fill region: [OFF_LAB, OFF_PV) = 51,840,000 floats = 12,960,000 float4
#define ZERO_N4  12960000
#define ZERO_BLOCKS 4736

#define VALID_BIT 0x80000000u

#define EXP_BLOCKS 1184
#define EXP_WARPS  (EXP_BLOCKS * 8)

// packed per-row scratch: {mask|valid, cls, sh_bits, so_bits}
__device__ uint4 g_meta[BM];

// IoU(a,b) > th  without division (denominator strictly positive)
__device__ __forceinline__ bool iou_gt(float4 a, float4 b, float th) {
    float area_a = (a.z - a.x) * (a.w - a.y);
    float area_b = (b.z - b.x) * (b.w - b.y);
    float w = fmaxf(fminf(a.z, b.z) - fmaxf(a.x, b.x), 0.0f);
    float h = fmaxf(fminf(a.w, b.w) - fmaxf(a.y, b.y), 0.0f);
    float inter = w * h;
    return inter > th * (area_a + area_b - inter + 1e-7f);
}
__device__ __forceinline__ bool iou_ge(float4 a, float4 b, float th) {
    float area_a = (a.z - a.x) * (a.w - a.y);
    float area_b = (b.z - b.x) * (b.w - b.y);
    float w = fmaxf(fminf(a.z, b.z) - fmaxf(a.x, b.x), 0.0f);
    float h = fmaxf(fminf(a.w, b.w) - fmaxf(a.y, b.y), 0.0f);
    float inter = w * h;
    return inter >= th * (area_a + area_b - inter + 1e-7f);
}

// ============================================================
// Kernel 1 (fused): blocks [0,64) = per-image selection (fast,
// warp-ballot formulation); blocks [64, 64+4736) = zero-fill.
// ============================================================
__global__ __launch_bounds__(256)
void pairgen_fused_kernel(const float* __restrict__ boxes,
                          const float* __restrict__ scores,
                          const int*   __restrict__ labels,
                          const float* __restrict__ tbh,
                          const float* __restrict__ tbo,
                          float* __restrict__ out) {
    // ---------------- zero-fill path ----------------
    if (blockIdx.x >= BB) {
        float4* p = (float4*)(out + OFF_LAB);
        const int stride = ZERO_BLOCKS * 256;
        const float4 z = make_float4(0.f, 0.f, 0.f, 0.f);
        for (int i = (blockIdx.x - BB) * 256 + threadIdx.x; i < ZERO_N4; i += stride)
            p[i] = z;
        return;
    }

    // ---------------- select path (one block per image) ----------------
    __shared__ float4 sb[NN];
    __shared__ float  ss[NN];
    __shared__ int    sl[NN];
    __shared__ uint4  adjv[NN];
    __shared__ int    order[NN];
    __shared__ unsigned int keptMask[4];
    __shared__ float  spk[NN];
    __shared__ float4 coords[NMAX];
    __shared__ int    labp[NMAX];
    __shared__ float  scp[NMAX];
    __shared__ int    s_nh, s_nt, s_nvalid;
    __shared__ float4 stbh[TT], stbo[TT];
    __shared__ unsigned int mbits_h[NMAX], mbits_o[NMAX];
    __shared__ float  pw[NMAX];

    const int b    = blockIdx.x;
    const int tid  = threadIdx.x;
    const int wid  = tid >> 5;
    const int lane = tid & 31;

    // ---- load per-image data ----
    if (tid < NN) {
        sb[tid] = ((const float4*)boxes)[b * NN + tid];
        ss[tid] = scores[b * NN + tid];
        sl[tid] = labels[b * NN + tid];
    }
    if (tid >= NN && tid < NN + TT) {
        stbh[tid - NN] = ((const float4*)tbh)[b * TT + (tid - NN)];
        stbo[tid - NN] = ((const float4*)tbo)[b * TT + (tid - NN)];
    }
    __syncthreads();

    // ---- phase 2: rank + NMS adjacency (warp per i, ballot over j) ----
    for (int i = wid; i < NN; i += 8) {
        const float4 bi = sb[i];          // broadcast
        const float  si = ss[i];
        const int    li = sl[i];
        const float  ki = (si >= SCORE_TH) ? si : -1.0f;
        int r = 0;
        unsigned int m0, m1, m2, m3;
        #pragma unroll
        for (int k = 0; k < 4; k++) {
            const int j = lane + 32 * k;
            const float sj = ss[j];
            const float kj = (sj >= SCORE_TH) ? sj : -1.0f;
            const bool rc = (kj > ki) || (kj == ki && j < i);
            r += __popc(__ballot_sync(0xffffffffu, rc));
            const bool sup = (sl[j] == li) && iou_gt(bi, sb[j], NMS_TH);
            const unsigned int bal = __ballot_sync(0xffffffffu, sup);
            if (k == 0) m0 = bal; else if (k == 1) m1 = bal;
            else if (k == 2) m2 = bal; else m3 = bal;
        }
        if (lane == 0) {
            order[r] = i;
            adjv[i] = make_uint4(m0, m1, m2, m3);
        }
    }
    if (wid == 0) {
        int c = 0;
        #pragma unroll
        for (int k = 0; k < 4; k++)
            c += __popc(__ballot_sync(0xffffffffu, ss[lane + 32 * k] >= SCORE_TH));
        if (lane == 0) { s_nvalid = c; s_nh = 0; s_nt = 0; }
    }
    __syncthreads();

    // ---- phase 3: serial greedy NMS scan (thread 0, prefetched) ----
    if (tid == 0) {
        unsigned int sup0 = 0, sup1 = 0, sup2 = 0, sup3 = 0;
        unsigned int k0 = 0, k1 = 0, k2 = 0, k3 = 0;
        const int nv = s_nvalid;
        if (nv > 0) {
            int idx = order[0];
            uint4 a = adjv[idx];
            for (int i = 0; i < nv; i++) {
                const int nidx = (i + 1 < nv) ? order[i + 1] : 0;
                const uint4 na = adjv[nidx];
                const int w = idx >> 5;
                const unsigned int bit = 1u << (idx & 31);
                const unsigned int sw = (w == 0) ? sup0 : (w == 1) ? sup1
                                        : (w == 2) ? sup2 : sup3;
                if (!(sw & bit)) {
                    if (w == 0) k0 |= bit; else if (w == 1) k1 |= bit;
                    else if (w == 2) k2 |= bit; else k3 |= bit;
                    sup0 |= a.x; sup1 |= a.y; sup2 |= a.z; sup3 |= a.w;
                }
                idx = nidx; a = na;
            }
        }
        keptMask[0] = k0; keptMask[1] = k1; keptMask[2] = k2; keptMask[3] = k3;
    }
    __syncthreads();

    // ---- phase 4: top-k per group (warp per i, ballot ranks) ----
    for (int i = wid; i < NN; i += 8) {
        const bool kept_i = (keptMask[i >> 5] >> (i & 31)) & 1u;
        const bool ish_i  = (sl[i] == HUMAN_IDX);
        const float si    = ss[i];
        int rh = 0, ro = 0;
        #pragma unroll
        for (int k = 0; k < 4; k++) {
            const int j = lane + 32 * k;
            const bool keptj = (keptMask[k] >> lane) & 1u;
            const bool ishj  = (sl[j] == HUMAN_IDX);
            const float sj   = ss[j];
            const bool better = (sj > si) || (sj == si && j < i);
            const bool kb = keptj && better;
            rh += __popc(__ballot_sync(0xffffffffu, kb &&  ishj));
            ro += __popc(__ballot_sync(0xffffffffu, kb && !ishj));
        }
        if (lane == 0) {
            const bool selh = kept_i &&  ish_i && (rh < MAX_H);
            const bool selo = kept_i && !ish_i && (ro < MAX_O);
            spk[i] = selh ? -si : (selo ? (2.0f - si) : 1e9f);
            if (selh) atomicAdd(&s_nh, 1);
            if (selh || selo) atomicAdd(&s_nt, 1);
        }
    }
    __syncthreads();

    // ---- phase 5: permutation rank (warp per i, ballot) ----
    for (int i = wid; i < NN; i += 8) {
        const float pki = spk[i];
        int pr = 0;
        #pragma unroll
        for (int k = 0; k < 4; k++) {
            const int j = lane + 32 * k;
            const float pkj = spk[j];
            pr += __popc(__ballot_sync(0xffffffffu,
                        (pkj < pki) || (pkj == pki && j < i)));
        }
        if (lane == 0 && pr < NMAX) {
            coords[pr] = sb[i];
            labp[pr]   = sl[i];
            scp[pr]    = ss[i];
        }
    }
    __syncthreads();

    // ---- phase 6: per-index GT-match bitmasks and s^p ----
    if (tid < NMAX) {
        const float4 c = coords[tid];
        unsigned int bh = 0, bo = 0;
        #pragma unroll
        for (int t = 0; t < TT; t++) {
            if (iou_ge(c, stbh[t], 0.5f)) bh |= (1u << t);
            if (iou_ge(c, stbo[t], 0.5f)) bo |= (1u << t);
        }
        mbits_h[tid] = bh;
        mbits_o[tid] = bo;
        pw[tid] = __powf(scp[tid], PEXP);
    }
    __syncthreads();

    const int nh = s_nh;
    const int nt = s_nt;

    // ---- phase 7: pair grid, small outputs + packed scratch ----
    float4* out_bh  = (float4*)(out + OFF_BH);
    float4* out_bo  = (float4*)(out + OFF_BO);
    float*  out_cls = out + OFF_CLS;
    float*  out_pv  = out + OFF_PV;

    for (int m = tid; m < MM; m += 256) {
        const int x = m / NMAX;
        const int y = m - x * NMAX;
        const bool pv = (x < nh) && (y < nt) && (x != y);
        float4 bh = make_float4(0.f, 0.f, 0.f, 0.f);
        float4 bo = bh;
        uint4 meta = make_uint4(0u, 0u, 0u, 0u);
        int cls = 0;
        if (pv) {
            bh = coords[x];
            bo = coords[y];
            cls = labp[y];
            meta.x = (mbits_h[x] & mbits_o[y]) | VALID_BIT;
            meta.y = (unsigned int)cls;
            meta.z = __float_as_uint(pw[x]);
            meta.w = __float_as_uint(pw[y]);
        }
        const int row = b * MM + m;
        out_bh[row]  = bh;
        out_bo[row]  = bo;
        out_cls[row] = pv ? (float)cls : 0.0f;
        out_pv[row]  = pv ? 1.0f : 0.0f;
        g_meta[row]  = meta;
    }
}

// ============================================================
// Kernel 2: expand valid rows (grid-stride, warp per row)
// ============================================================
__global__ __launch_bounds__(256)
void pairgen_expand_kernel(const int* __restrict__ gt_labels,
                           const float* __restrict__ mapping,
                           float* __restrict__ out) {
    const int wid  = threadIdx.x >> 5;
    const int lane = threadIdx.x & 31;
    __shared__ unsigned int bmp[8][20];

    for (int row = blockIdx.x * 8 + wid; row < BM; row += EXP_WARPS) {
        const uint4 meta = g_meta[row];
        if (!(meta.x & VALID_BIT)) continue;    // invalid: already zero-filled

        const int b    = row / MM;
        const int m    = row - b * MM;
        const unsigned int mask = meta.x;
        const int   cls = (int)meta.y;
        const float sh  = __uint_as_float(meta.z);
        const float so  = __uint_as_float(meta.w);

        float4* lab = (float4*)(out + OFF_LAB) + (size_t)row * 150;
        float4* pr0 = (float4*)(out + OFF_PRI) + ((size_t)b * 2 * MM + m) * 150;
        float4* pr1 = pr0 + (size_t)MM * 150;

        if (lane < 19) bmp[wid][lane] = 0;
        __syncwarp();
        if (lane < TT && ((mask >> lane) & 1u)) {
            int c = gt_labels[b * TT + lane];
            atomicOr(&bmp[wid][c >> 5], 1u << (c & 31));
        }
        __syncwarp();

        const float4* mr = (const float4*)(mapping + cls * NUM_CLS);
        #pragma unroll
        for (int i = lane; i < 150; i += 32) {
            const float4 mv = mr[i];
            pr0[i] = make_float4(mv.x * sh, mv.y * sh, mv.z * sh, mv.w * sh);
            pr1[i] = make_float4(mv.x * so, mv.y * so, mv.z * so, mv.w * so);
            const int c = i * 4;
            float4 lv;
            lv.x = ((bmp[wid][(c + 0) >> 5] >> ((c + 0) & 31)) & 1u) ? 1.0f : 0.0f;
            lv.y = ((bmp[wid][(c + 1) >> 5] >> ((c + 1) & 31)) & 1u) ? 1.0f : 0.0f;
            lv.z = ((bmp[wid][(c + 2) >> 5] >> ((c + 2) & 31)) & 1u) ? 1.0f : 0.0f;
            lv.w = ((bmp[wid][(c + 3) >> 5] >> ((c + 3) & 31)) & 1u) ? 1.0f : 0.0f;
            lab[i] = lv;
        }
        __syncwarp();
    }
}

extern "C" void kernel_launch(void* const* d_in, const int* in_sizes, int n_in,
                              void* d_out, int out_size) {
    const float* boxes     = (const float*)d_in[0];
    const float* scores    = (const float*)d_in[1];
    const int*   labels    = (const int*)  d_in[2];
    const float* t_boxes_h = (const float*)d_in[3];
    const float* t_boxes_o = (const float*)d_in[4];
    const int*   gt_labels = (const int*)  d_in[5];
    const float* mapping   = (const float*)d_in[6];
    float* out = (float*)d_out;

    pairgen_fused_kernel<<<BB + ZERO_BLOCKS, 256>>>(boxes, scores, labels,
                                                    t_boxes_h, t_boxes_o, out);
    pairgen_expand_kernel<<<EXP_BLOCKS, 256>>>(gt_labels, mapping, out);
}